// round 12
// baseline (speedup 1.0000x reference)
#include <cuda_runtime.h>

typedef unsigned long long u64;
typedef unsigned u32;
#define DI __device__ __forceinline__

// ---------- packed f32x2 helpers (PTX-only on sm_103a) ----------
DI u64 pack2(float lo, float hi) {
    u64 r;
    asm("mov.b64 %0, {%1, %2};"
        : "=l"(r) : "r"(__float_as_uint(lo)), "r"(__float_as_uint(hi)));
    return r;
}
DI u64 dup2(float v) {
    u64 r;
    asm("mov.b64 %0, {%1, %1};" : "=l"(r) : "r"(__float_as_uint(v)));
    return r;
}
DI void unpack2(u64 v, u32& lo, u32& hi) {
    asm("mov.b64 {%0, %1}, %2;" : "=r"(lo), "=r"(hi) : "l"(v));
}
DI u64 fma2(u64 a, u64 b, u64 c) {
    u64 d;
    asm("fma.rn.f32x2 %0, %1, %2, %3;" : "=l"(d) : "l"(a), "l"(b), "l"(c));
    return d;
}
DI u64 mul2(u64 a, u64 b) {
    u64 d;
    asm("mul.rn.f32x2 %0, %1, %2;" : "=l"(d) : "l"(a), "l"(b));
    return d;
}
DI u64 add2(u64 a, u64 b) {
    u64 d;
    asm("add.rn.f32x2 %0, %1, %2;" : "=l"(d) : "l"(a), "l"(b));
    return d;
}
DI u32 prmt(u32 a, u32 b, u32 sel) {
    u32 d;
    asm("prmt.b32 %0, %1, %2, %3;" : "=r"(d) : "r"(a), "r"(b), "r"(sel));
    return d;
}
// sign bytes of 4 floats -> [sA,sB,sC,sD] (0xFF where negative)
DI u32 sgn4(u32 a, u32 b, u32 c, u32 d) {
    const u32 ab = prmt(a, b, 0xFBFB);
    const u32 cd = prmt(c, d, 0xFBFB);
    return prmt(ab, cd, 0x5410);
}
DI u32 dp4a(u32 a, u32 b, u32 c) {
    u32 d;
    asm("dp4a.u32.u32 %0, %1, %2, %3;" : "=r"(d) : "r"(a), "r"(b), "r"(c));
    return d;
}
DI void prefetchL2(const void* p) {
    asm volatile("prefetch.global.L2 [%0];" :: "l"(p));
}

__global__ void __launch_bounds__(128, 6) toy_force_kernel(
    const float4* __restrict__ pos,
    const float*  __restrict__ W1,   // [8,2]
    const float*  __restrict__ b1,   // [8]
    const float*  __restrict__ W2,   // [4,8]
    const float*  __restrict__ b2,   // [4]
    const float*  __restrict__ W3,   // [2,4]
    float4*       __restrict__ out,
    int npairs)
{
    __shared__ float u_s[16][8];   // u(m2)_i = sum_{j act} (-v3_j) W2[j][i]
    __shared__ u64 tlo[256];       // force of m1[0:4] given m2
    __shared__ u64 thi[256];       // force of m1[4:8] given m2

    const int tid = threadIdx.x;

    // ---- u table: one (m2, i) per thread ----
    {
        const int i = tid & 7, m = tid >> 3;
        float s = 0.f;
#pragma unroll
        for (int j = 0; j < 4; j++) {
            const float v3n = -(__ldg(&W3[j]) + __ldg(&W3[4 + j]));  // fold -grad
            if (!((m >> j) & 1)) s += v3n * __ldg(&W2[8 * j + i]);
        }
        u_s[m][i] = s;
    }
    __syncthreads();

    // ---- split force tables: 512 entries ----
    for (int e = tid; e < 512; e += blockDim.x) {
        const bool hi = e >= 256;
        const int ent = e & 255;
        const int m1h = ent & 15, m2 = ent >> 4;
        const int base = hi ? 4 : 0;
        float fx = 0.f, fy = 0.f;
#pragma unroll
        for (int k = 0; k < 4; k++) {
            const int i = base + k;
            const float msk = ((m1h >> k) & 1) ? 0.f : 1.f;
            const float ui = msk * u_s[m2][i];
            fx = fmaf(ui, __ldg(&W1[2 * i]), fx);
            fy = fmaf(ui, __ldg(&W1[2 * i + 1]), fy);
        }
        (hi ? thi : tlo)[ent] = pack2(fx, fy);
    }
    __syncthreads();

    // ---- hoist compact packed weights into registers (30 u64 = 60 regs) ----
    u64 W1px[4], W1py[4], B1p[4], W2p[2][8], B2p[2];
#pragma unroll
    for (int k = 0; k < 4; k++) {
        W1px[k] = pack2(__ldg(&W1[4 * k]),     __ldg(&W1[4 * k + 2]));
        W1py[k] = pack2(__ldg(&W1[4 * k + 1]), __ldg(&W1[4 * k + 3]));
        B1p[k]  = pack2(__ldg(&b1[2 * k]),     __ldg(&b1[2 * k + 1]));
    }
#pragma unroll
    for (int a = 0; a < 2; a++) {
#pragma unroll
        for (int i = 0; i < 8; i++)
            W2p[a][i] = pack2(__ldg(&W2[16 * a + i]), __ldg(&W2[16 * a + 8 + i]));
        B2p[a] = pack2(__ldg(&b2[2 * a]), __ldg(&b2[2 * a + 1]));
    }

    const char* tl = (const char*)tlo;
    const char* th = (const char*)thi;
    const u32 K1 = 0x40201008u;   // byte weights 8,16,32,64 (m1 bits * 8B)
    const u32 K2 = 0x08040201u;   // byte weights 1,2,4,8    (m2 value)
    const u32 ONES = 0x01010101u;

    // one 2-D position -> packed force (f32x2)
    auto evalPos = [&](float x, float y) -> u64 {
        const u64 X = dup2(x), Y = dup2(y);
        u32 z[8];
#pragma unroll
        for (int k = 0; k < 4; k++) {
            const u64 zp = fma2(W1px[k], X, fma2(W1py[k], Y, B1p[k]));
            unpack2(zp, z[2 * k], z[2 * k + 1]);
        }
        u64 HD[8];
#pragma unroll
        for (int i = 0; i < 8; i++)
            HD[i] = dup2(fmaxf(__uint_as_float(z[i]), 0.f));
        u32 z2v[4];
#pragma unroll
        for (int a = 0; a < 2; a++) {
            u64 acc0 = fma2(W2p[a][0], HD[0], B2p[a]);
            acc0 = fma2(W2p[a][1], HD[1], acc0);
            acc0 = fma2(W2p[a][2], HD[2], acc0);
            acc0 = fma2(W2p[a][3], HD[3], acc0);
            u64 acc1 = mul2(W2p[a][4], HD[4]);
            acc1 = fma2(W2p[a][5], HD[5], acc1);
            acc1 = fma2(W2p[a][6], HD[6], acc1);
            acc1 = fma2(W2p[a][7], HD[7], acc1);
            unpack2(add2(acc0, acc1), z2v[2 * a], z2v[2 * a + 1]);
        }
        const u32 d1a = dp4a(sgn4(z[0], z[1], z[2], z[3]) & K1, ONES, 0);
        const u32 d1b = dp4a(sgn4(z[4], z[5], z[6], z[7]) & K1, ONES, 0);
        const u32 m2s = dp4a(sgn4(z2v[0], z2v[1], z2v[2], z2v[3]) & K2, ONES, 0) << 7;
        return add2(*(const u64*)(tl + (d1a + m2s)),
                    *(const u64*)(th + (d1b + m2s)));
    };

    const int stride = gridDim.x * blockDim.x;

    // ---- grid-stride, 2 float4 streams, depth-1 reg prefetch + L2 prefetch ----
    int ka = blockIdx.x * blockDim.x + tid;
    if (ka >= npairs) return;
    int kb = ka + stride;
    bool hb = kb < npairs;

    float4 pa = pos[ka];
    float4 pb = hb ? pos[kb] : pa;

    for (;;) {
        const int kan = ka + 2 * stride;
        const int kbn = kb + 2 * stride;
        const bool han = kan < npairs;
        const bool hbn = hb && (kbn < npairs);

        // L2 prefetch two iterations ahead (hint; clamped in-bounds)
        const int kpa = min(ka + 4 * stride, npairs - 1);
        const int kpb = min(kb + 4 * stride, npairs - 1);
        prefetchL2(pos + kpa);
        prefetchL2(pos + kpb);

        float4 na, nb;
        if (han) na = pos[kan];
        if (hbn) nb = pos[kbn];

        {
            const u64 F0 = evalPos(pa.x, pa.y);
            const u64 F1 = evalPos(pa.z, pa.w);
            __stcs((ulonglong2*)&out[ka], make_ulonglong2(F0, F1));
        }
        if (hb) {
            const u64 G0 = evalPos(pb.x, pb.y);
            const u64 G1 = evalPos(pb.z, pb.w);
            __stcs((ulonglong2*)&out[kb], make_ulonglong2(G0, G1));
        }

        if (!han) break;
        pa = na;
        pb = hbn ? nb : na;
        ka = kan;
        kb = kbn;
        hb = hbn;
    }
}

extern "C" void kernel_launch(void* const* d_in, const int* in_sizes, int n_in,
                              void* d_out, int out_size) {
    const float* pos = (const float*)d_in[0];
    const float* W1  = (const float*)d_in[1];
    const float* b1  = (const float*)d_in[2];
    const float* W2  = (const float*)d_in[3];
    const float* b2  = (const float*)d_in[4];
    const float* W3  = (const float*)d_in[5];
    float* out = (float*)d_out;

    const int npairs = in_sizes[0] / 4;   // one float4 = 2 positions

    const int threads = 128;
    const int blocks  = 888;              // 148 SMs x 6 CTAs
    toy_force_kernel<<<blocks, threads>>>(
        (const float4*)pos, W1, b1, W2, b2, W3, (float4*)out, npairs);
}

// round 13
// speedup vs baseline: 1.2040x; 1.2040x over previous
#include <cuda_runtime.h>

typedef unsigned long long u64;
typedef unsigned u32;
#define DI __device__ __forceinline__

// ---------- packed f32x2 helpers (PTX-only on sm_103a) ----------
DI u64 pack2(float lo, float hi) {
    u64 r;
    asm("mov.b64 %0, {%1, %2};"
        : "=l"(r) : "r"(__float_as_uint(lo)), "r"(__float_as_uint(hi)));
    return r;
}
DI u64 dup2(float v) {
    u64 r;
    asm("mov.b64 %0, {%1, %1};" : "=l"(r) : "r"(__float_as_uint(v)));
    return r;
}
DI void unpack2(u64 v, u32& lo, u32& hi) {
    asm("mov.b64 {%0, %1}, %2;" : "=r"(lo), "=r"(hi) : "l"(v));
}
DI u64 fma2(u64 a, u64 b, u64 c) {
    u64 d;
    asm("fma.rn.f32x2 %0, %1, %2, %3;" : "=l"(d) : "l"(a), "l"(b), "l"(c));
    return d;
}
DI u64 mul2(u64 a, u64 b) {
    u64 d;
    asm("mul.rn.f32x2 %0, %1, %2;" : "=l"(d) : "l"(a), "l"(b));
    return d;
}
DI u64 add2(u64 a, u64 b) {
    u64 d;
    asm("add.rn.f32x2 %0, %1, %2;" : "=l"(d) : "l"(a), "l"(b));
    return d;
}
DI u32 prmt(u32 a, u32 b, u32 sel) {
    u32 d;
    asm("prmt.b32 %0, %1, %2, %3;" : "=r"(d) : "r"(a), "r"(b), "r"(sel));
    return d;
}
// sign bytes of 4 floats -> [sA,sB,sC,sD] (0xFF where negative)
DI u32 sgn4(u32 a, u32 b, u32 c, u32 d) {
    const u32 ab = prmt(a, b, 0xFBFB);
    const u32 cd = prmt(c, d, 0xFBFB);
    return prmt(ab, cd, 0x5410);
}
DI u32 dp4a(u32 a, u32 b, u32 c) {
    u32 d;
    asm("dp4a.u32.u32 %0, %1, %2, %3;" : "=r"(d) : "r"(a), "r"(b), "r"(c));
    return d;
}

__global__ void __launch_bounds__(128, 6) toy_force_kernel(
    const float4* __restrict__ pos,
    const float*  __restrict__ W1,   // [8,2]
    const float*  __restrict__ b1,   // [8]
    const float*  __restrict__ W2,   // [4,8]
    const float*  __restrict__ b2,   // [4]
    const float*  __restrict__ W3,   // [2,4]
    float4*       __restrict__ out,
    int npairs)
{
    __shared__ float u_s[16][8];   // u(m2)_i = sum_{j act} (-v3_j) W2[j][i]
    __shared__ u64 tlo[256];       // force of m1[0:4] given m2
    __shared__ u64 thi[256];       // force of m1[4:8] given m2

    const int tid = threadIdx.x;

    // ---- u table: one (m2, i) per thread ----
    {
        const int i = tid & 7, m = tid >> 3;
        float s = 0.f;
#pragma unroll
        for (int j = 0; j < 4; j++) {
            const float v3n = -(__ldg(&W3[j]) + __ldg(&W3[4 + j]));  // fold -grad
            if (!((m >> j) & 1)) s += v3n * __ldg(&W2[8 * j + i]);
        }
        u_s[m][i] = s;
    }
    __syncthreads();

    // ---- split force tables: 512 entries ----
    for (int e = tid; e < 512; e += blockDim.x) {
        const bool hi = e >= 256;
        const int ent = e & 255;
        const int m1h = ent & 15, m2 = ent >> 4;
        const int base = hi ? 4 : 0;
        float fx = 0.f, fy = 0.f;
#pragma unroll
        for (int k = 0; k < 4; k++) {
            const int i = base + k;
            const float msk = ((m1h >> k) & 1) ? 0.f : 1.f;
            const float ui = msk * u_s[m2][i];
            fx = fmaf(ui, __ldg(&W1[2 * i]), fx);
            fy = fmaf(ui, __ldg(&W1[2 * i + 1]), fy);
        }
        (hi ? thi : tlo)[ent] = pack2(fx, fy);
    }
    __syncthreads();

    // ---- hoist compact packed weights into registers (30 u64 = 60 regs) ----
    u64 W1px[4], W1py[4], B1p[4], W2p[2][8], B2p[2];
#pragma unroll
    for (int k = 0; k < 4; k++) {
        W1px[k] = pack2(__ldg(&W1[4 * k]),     __ldg(&W1[4 * k + 2]));
        W1py[k] = pack2(__ldg(&W1[4 * k + 1]), __ldg(&W1[4 * k + 3]));
        B1p[k]  = pack2(__ldg(&b1[2 * k]),     __ldg(&b1[2 * k + 1]));
    }
#pragma unroll
    for (int a = 0; a < 2; a++) {
#pragma unroll
        for (int i = 0; i < 8; i++)
            W2p[a][i] = pack2(__ldg(&W2[16 * a + i]), __ldg(&W2[16 * a + 8 + i]));
        B2p[a] = pack2(__ldg(&b2[2 * a]), __ldg(&b2[2 * a + 1]));
    }

    const char* tl = (const char*)tlo;
    const char* th = (const char*)thi;
    const u32 K1 = 0x40201008u;   // byte weights 8,16,32,64 (m1 bits * 8B)
    const u32 K2 = 0x08040201u;   // byte weights 1,2,4,8    (m2 value)
    const u32 ONES = 0x01010101u;

    // one 2-D position -> packed force (f32x2)
    auto evalPos = [&](float x, float y) -> u64 {
        const u64 X = dup2(x), Y = dup2(y);
        u32 z[8];
#pragma unroll
        for (int k = 0; k < 4; k++) {
            const u64 zp = fma2(W1px[k], X, fma2(W1py[k], Y, B1p[k]));
            unpack2(zp, z[2 * k], z[2 * k + 1]);
        }
        u64 HD[8];
#pragma unroll
        for (int i = 0; i < 8; i++)
            HD[i] = dup2(fmaxf(__uint_as_float(z[i]), 0.f));
        u32 z2v[4];
#pragma unroll
        for (int a = 0; a < 2; a++) {
            u64 acc0 = fma2(W2p[a][0], HD[0], B2p[a]);
            acc0 = fma2(W2p[a][1], HD[1], acc0);
            acc0 = fma2(W2p[a][2], HD[2], acc0);
            acc0 = fma2(W2p[a][3], HD[3], acc0);
            u64 acc1 = mul2(W2p[a][4], HD[4]);
            acc1 = fma2(W2p[a][5], HD[5], acc1);
            acc1 = fma2(W2p[a][6], HD[6], acc1);
            acc1 = fma2(W2p[a][7], HD[7], acc1);
            unpack2(add2(acc0, acc1), z2v[2 * a], z2v[2 * a + 1]);
        }
        const u32 d1a = dp4a(sgn4(z[0], z[1], z[2], z[3]) & K1, ONES, 0);
        const u32 d1b = dp4a(sgn4(z[4], z[5], z[6], z[7]) & K1, ONES, 0);
        const u32 m2s = dp4a(sgn4(z2v[0], z2v[1], z2v[2], z2v[3]) & K2, ONES, 0) << 7;
        return add2(*(const u64*)(tl + (d1a + m2s)),
                    *(const u64*)(th + (d1b + m2s)));
    };

    const int stride = gridDim.x * blockDim.x;

    // ---- grid-stride, 3 float4 streams, rotating register prefetch ----
    int ka = blockIdx.x * blockDim.x + tid;
    if (ka >= npairs) return;
    int kb = ka + stride;
    int kc = kb + stride;
    bool hb = kb < npairs;
    bool hc = kc < npairs;

    float4 pa = pos[ka];
    float4 pb = hb ? pos[kb] : pa;
    float4 pc = hc ? pos[kc] : pa;

    for (;;) {
        const int kan = ka + 3 * stride;
        const int kbn = kb + 3 * stride;
        const int kcn = kc + 3 * stride;
        const bool han = kan < npairs;
        const bool hbn = hb && (kbn < npairs);
        const bool hcn = hc && (kcn < npairs);
        float4 na, nb, nc;
        if (han) na = pos[kan];
        if (hbn) nb = pos[kbn];
        if (hcn) nc = pos[kcn];

        {
            const u64 F0 = evalPos(pa.x, pa.y);
            const u64 F1 = evalPos(pa.z, pa.w);
            *(ulonglong2*)&out[ka] = make_ulonglong2(F0, F1);
        }
        if (hb) {
            const u64 G0 = evalPos(pb.x, pb.y);
            const u64 G1 = evalPos(pb.z, pb.w);
            *(ulonglong2*)&out[kb] = make_ulonglong2(G0, G1);
        }
        if (hc) {
            const u64 H0 = evalPos(pc.x, pc.y);
            const u64 H1 = evalPos(pc.z, pc.w);
            *(ulonglong2*)&out[kc] = make_ulonglong2(H0, H1);
        }

        if (!han) break;
        pa = na;
        pb = hbn ? nb : na;
        pc = hcn ? nc : na;
        ka = kan;
        kb = kbn;
        kc = kcn;
        hb = hbn;
        hc = hcn;
    }
}

extern "C" void kernel_launch(void* const* d_in, const int* in_sizes, int n_in,
                              void* d_out, int out_size) {
    const float* pos = (const float*)d_in[0];
    const float* W1  = (const float*)d_in[1];
    const float* b1  = (const float*)d_in[2];
    const float* W2  = (const float*)d_in[3];
    const float* b2  = (const float*)d_in[4];
    const float* W3  = (const float*)d_in[5];
    float* out = (float*)d_out;

    const int npairs = in_sizes[0] / 4;   // one float4 = 2 positions

    const int threads = 128;
    const int blocks  = 888;              // 148 SMs x 6 CTAs
    toy_force_kernel<<<blocks, threads>>>(
        (const float4*)pos, W1, b1, W2, b2, W3, (float4*)out, npairs);
}

// round 14
// speedup vs baseline: 1.2183x; 1.0118x over previous
#include <cuda_runtime.h>

typedef unsigned long long u64;
typedef unsigned u32;
#define DI __device__ __forceinline__

// ---------- packed f32x2 helpers (PTX-only on sm_103a) ----------
DI u64 pack2(float lo, float hi) {
    u64 r;
    asm("mov.b64 %0, {%1, %2};"
        : "=l"(r) : "r"(__float_as_uint(lo)), "r"(__float_as_uint(hi)));
    return r;
}
DI u64 dup2(float v) {
    u64 r;
    asm("mov.b64 %0, {%1, %1};" : "=l"(r) : "r"(__float_as_uint(v)));
    return r;
}
DI void unpack2(u64 v, u32& lo, u32& hi) {
    asm("mov.b64 {%0, %1}, %2;" : "=r"(lo), "=r"(hi) : "l"(v));
}
DI u64 fma2(u64 a, u64 b, u64 c) {
    u64 d;
    asm("fma.rn.f32x2 %0, %1, %2, %3;" : "=l"(d) : "l"(a), "l"(b), "l"(c));
    return d;
}
DI u64 mul2(u64 a, u64 b) {
    u64 d;
    asm("mul.rn.f32x2 %0, %1, %2;" : "=l"(d) : "l"(a), "l"(b));
    return d;
}
DI u64 add2(u64 a, u64 b) {
    u64 d;
    asm("add.rn.f32x2 %0, %1, %2;" : "=l"(d) : "l"(a), "l"(b));
    return d;
}
DI u32 prmt(u32 a, u32 b, u32 sel) {
    u32 d;
    asm("prmt.b32 %0, %1, %2, %3;" : "=r"(d) : "r"(a), "r"(b), "r"(sel));
    return d;
}
// sign bytes of 4 floats -> [sA,sB,sC,sD] (0xFF where negative)
DI u32 sgn4(u32 a, u32 b, u32 c, u32 d) {
    const u32 ab = prmt(a, b, 0xFBFB);
    const u32 cd = prmt(c, d, 0xFBFB);
    return prmt(ab, cd, 0x5410);
}
DI u32 dp4a(u32 a, u32 b, u32 c) {
    u32 d;
    asm("dp4a.u32.u32 %0, %1, %2, %3;" : "=r"(d) : "r"(a), "r"(b), "r"(c));
    return d;
}

__global__ void __launch_bounds__(128, 6) toy_force_kernel(
    const float4* __restrict__ pos,
    const float*  __restrict__ W1,   // [8,2]
    const float*  __restrict__ b1,   // [8]
    const float*  __restrict__ W2,   // [4,8]
    const float*  __restrict__ b2,   // [4]
    const float*  __restrict__ W3,   // [2,4]
    float4*       __restrict__ out,
    int npairs)
{
    __shared__ float u_s[16][8];   // u(m2)_i = sum_{j act} (-v3_j) W2[j][i]
    __shared__ u64 tlo[256];       // force of m1[0:4] given m2
    __shared__ u64 thi[256];       // force of m1[4:8] given m2

    const int tid = threadIdx.x;

    // ---- u table: one (m2, i) per thread ----
    {
        const int i = tid & 7, m = tid >> 3;
        float s = 0.f;
#pragma unroll
        for (int j = 0; j < 4; j++) {
            const float v3n = -(__ldg(&W3[j]) + __ldg(&W3[4 + j]));  // fold -grad
            if (!((m >> j) & 1)) s += v3n * __ldg(&W2[8 * j + i]);
        }
        u_s[m][i] = s;
    }
    __syncthreads();

    // ---- split force tables: 512 entries ----
    for (int e = tid; e < 512; e += blockDim.x) {
        const bool hi = e >= 256;
        const int ent = e & 255;
        const int m1h = ent & 15, m2 = ent >> 4;
        const int base = hi ? 4 : 0;
        float fx = 0.f, fy = 0.f;
#pragma unroll
        for (int k = 0; k < 4; k++) {
            const int i = base + k;
            const float msk = ((m1h >> k) & 1) ? 0.f : 1.f;
            const float ui = msk * u_s[m2][i];
            fx = fmaf(ui, __ldg(&W1[2 * i]), fx);
            fy = fmaf(ui, __ldg(&W1[2 * i + 1]), fy);
        }
        (hi ? thi : tlo)[ent] = pack2(fx, fy);
    }
    __syncthreads();

    // ---- register-resident weights, all neuron-pair packed (28 u64 + 4 f32) ----
    u64 W1px[4], W1py[4], B1p[4], W2np[4][4];
    float b2s[4];
#pragma unroll
    for (int k = 0; k < 4; k++) {
        W1px[k] = pack2(__ldg(&W1[4 * k]),     __ldg(&W1[4 * k + 2]));
        W1py[k] = pack2(__ldg(&W1[4 * k + 1]), __ldg(&W1[4 * k + 3]));
        B1p[k]  = pack2(__ldg(&b1[2 * k]),     __ldg(&b1[2 * k + 1]));
    }
#pragma unroll
    for (int j = 0; j < 4; j++) {
#pragma unroll
        for (int k = 0; k < 4; k++)
            W2np[j][k] = pack2(__ldg(&W2[8 * j + 2 * k]),
                               __ldg(&W2[8 * j + 2 * k + 1]));
        b2s[j] = __ldg(&b2[j]);
    }

    const char* tl = (const char*)tlo;
    const char* th = (const char*)thi;
    const u32 K1 = 0x40201008u;   // byte weights 8,16,32,64 (m1 bits * 8B)
    const u32 K2 = 0x08040201u;   // byte weights 1,2,4,8    (m2 value)
    const u32 ONES = 0x01010101u;

    // one 2-D position -> packed force (f32x2); layer2 consumes neuron-pair h
    auto evalPos = [&](float x, float y) -> u64 {
        const u64 X = dup2(x), Y = dup2(y);
        u32 z[8];
        u64 Hp[4];
#pragma unroll
        for (int k = 0; k < 4; k++) {
            const u64 zp = fma2(W1px[k], X, fma2(W1py[k], Y, B1p[k]));
            unpack2(zp, z[2 * k], z[2 * k + 1]);
            Hp[k] = pack2(fmaxf(__uint_as_float(z[2 * k]), 0.f),
                          fmaxf(__uint_as_float(z[2 * k + 1]), 0.f));
        }
        u32 z2v[4];
#pragma unroll
        for (int j = 0; j < 4; j++) {
            u64 acc = mul2(W2np[j][0], Hp[0]);
            acc = fma2(W2np[j][1], Hp[1], acc);
            acc = fma2(W2np[j][2], Hp[2], acc);
            acc = fma2(W2np[j][3], Hp[3], acc);
            u32 lo, hi;
            unpack2(acc, lo, hi);
            const float zj = (__uint_as_float(lo) + __uint_as_float(hi)) + b2s[j];
            z2v[j] = __float_as_uint(zj);
        }
        const u32 d1a = dp4a(sgn4(z[0], z[1], z[2], z[3]) & K1, ONES, 0);
        const u32 d1b = dp4a(sgn4(z[4], z[5], z[6], z[7]) & K1, ONES, 0);
        const u32 m2s = dp4a(sgn4(z2v[0], z2v[1], z2v[2], z2v[3]) & K2, ONES, 0) << 7;
        return add2(*(const u64*)(tl + (d1a + m2s)),
                    *(const u64*)(th + (d1b + m2s)));
    };

    const int stride = gridDim.x * blockDim.x;

    // ---- grid-stride, 3 float4 streams, rotating register prefetch ----
    int ka = blockIdx.x * blockDim.x + tid;
    if (ka >= npairs) return;
    int kb = ka + stride;
    int kc = kb + stride;
    bool hb = kb < npairs;
    bool hc = kc < npairs;

    float4 pa = pos[ka];
    float4 pb = hb ? pos[kb] : pa;
    float4 pc = hc ? pos[kc] : pa;

    for (;;) {
        const int kan = ka + 3 * stride;
        const int kbn = kb + 3 * stride;
        const int kcn = kc + 3 * stride;
        const bool han = kan < npairs;
        const bool hbn = hb && (kbn < npairs);
        const bool hcn = hc && (kcn < npairs);
        float4 na, nb, nc;
        if (han) na = pos[kan];
        if (hbn) nb = pos[kbn];
        if (hcn) nc = pos[kcn];

        {
            const u64 F0 = evalPos(pa.x, pa.y);
            const u64 F1 = evalPos(pa.z, pa.w);
            *(ulonglong2*)&out[ka] = make_ulonglong2(F0, F1);
        }
        if (hb) {
            const u64 G0 = evalPos(pb.x, pb.y);
            const u64 G1 = evalPos(pb.z, pb.w);
            *(ulonglong2*)&out[kb] = make_ulonglong2(G0, G1);
        }
        if (hc) {
            const u64 H0 = evalPos(pc.x, pc.y);
            const u64 H1 = evalPos(pc.z, pc.w);
            *(ulonglong2*)&out[kc] = make_ulonglong2(H0, H1);
        }

        if (!han) break;
        pa = na;
        pb = hbn ? nb : na;
        pc = hcn ? nc : na;
        ka = kan;
        kb = kbn;
        kc = kcn;
        hb = hbn;
        hc = hcn;
    }
}

extern "C" void kernel_launch(void* const* d_in, const int* in_sizes, int n_in,
                              void* d_out, int out_size) {
    const float* pos = (const float*)d_in[0];
    const float* W1  = (const float*)d_in[1];
    const float* b1  = (const float*)d_in[2];
    const float* W2  = (const float*)d_in[3];
    const float* b2  = (const float*)d_in[4];
    const float* W3  = (const float*)d_in[5];
    float* out = (float*)d_out;

    const int npairs = in_sizes[0] / 4;   // one float4 = 2 positions

    const int threads = 128;
    const int blocks  = 888;              // 148 SMs x 6 CTAs
    toy_force_kernel<<<blocks, threads>>>(
        (const float4*)pos, W1, b1, W2, b2, W3, (float4*)out, npairs);
}